// round 1
// baseline (speedup 1.0000x reference)
#include <cuda_runtime.h>

#define DD 256
#define NA_MAX (64*256)
#define NR_MAX (512*256)

// ---------------- scratch state (device globals; no allocation) ----------------
__device__ __align__(16) float gA [NA_MAX*DD];
__device__ __align__(16) float gR [NR_MAX*DD];
__device__ __align__(16) float gAq[NA_MAX*DD];
__device__ __align__(16) float gAk[NA_MAX*DD];
__device__ __align__(16) float gAv[NA_MAX*DD];
__device__ __align__(16) float gRq[NR_MAX*DD];
__device__ __align__(16) float gRk[NR_MAX*DD];
__device__ __align__(16) float gRv[NR_MAX*DD];
__device__ __align__(16) float gTA[NA_MAX*DD];
__device__ __align__(16) float gTR[NR_MAX*DD];
__device__ float gInvA[NA_MAX];
__device__ float gInvR[NR_MAX];

__device__ __forceinline__ float leaky_f(float x) { return x >= 0.f ? x : 0.1f * x; }
__device__ __forceinline__ float sigmoid_f(float x) {
    return __fdividef(1.f, 1.f + __expf(-x));
}

// ---------------- per-row 1/count scales ----------------
__global__ void fill_inv_kernel(const int* __restrict__ lig, const int* __restrict__ res) {
    int b = blockIdx.x;
    int as = lig[2*b], ac = lig[2*b+1];
    int rs = res[2*b], rc = res[2*b+1];
    float ia = 1.f / (float)rc;   // A rows divided by r_cnt
    float ir = 1.f / (float)ac;   // R rows divided by a_cnt
    for (int i = threadIdx.x; i < ac; i += blockDim.x) gInvA[as + i] = ia;
    for (int i = threadIdx.x; i < rc; i += blockDim.x) gInvR[rs + i] = ir;
}

// ---------------- GEMM: C[M,256] = X[M,256] @ W[256,256] (+epilogue) ----------------
// MODE 0: C = XW ; MODE 1: C = leaky(XW) ; MODE 2: C = leaky(XW)*scale[r] + base[r,c]
template <int MODE>
__global__ void gemm64_kernel(const float* __restrict__ X, const float* __restrict__ W,
                              float* __restrict__ C, int M,
                              const float* __restrict__ scale, const float* __restrict__ base)
{
    __shared__ float As[16][68];   // k-major (transposed X tile), stride 68 keeps float4 alignment
    __shared__ float Bs[16][68];
    const int row0 = blockIdx.x * 64;
    const int col0 = blockIdx.y * 64;
    const int tid = threadIdx.x;
    const int tn = tid & 15, tm = tid >> 4;   // 16 x 16 thread grid, 4x4 micro-tile
    const int lr = tid >> 2, lc = tid & 3;    // loader mapping: 64 rows x 4 float4-cols

    float acc[4][4] = {};

    for (int k0 = 0; k0 < DD; k0 += 16) {
        float4 xv = make_float4(0.f, 0.f, 0.f, 0.f);
        int grow = row0 + lr;
        if (grow < M) xv = *(const float4*)(X + grow * DD + k0 + lc * 4);
        As[lc*4+0][lr] = xv.x; As[lc*4+1][lr] = xv.y;
        As[lc*4+2][lr] = xv.z; As[lc*4+3][lr] = xv.w;

        float4 wv = *(const float4*)(W + (k0 + tm) * DD + col0 + tn * 4);
        *(float4*)&Bs[tm][tn * 4] = wv;
        __syncthreads();

        #pragma unroll
        for (int k = 0; k < 16; k++) {
            float a[4], b[4];
            *(float4*)a = *(const float4*)&As[k][tm * 4];
            *(float4*)b = *(const float4*)&Bs[k][tn * 4];
            #pragma unroll
            for (int i = 0; i < 4; i++)
                #pragma unroll
                for (int j = 0; j < 4; j++)
                    acc[i][j] += a[i] * b[j];
        }
        __syncthreads();
    }

    #pragma unroll
    for (int i = 0; i < 4; i++) {
        int r = row0 + tm * 4 + i;
        if (r >= M) continue;
        float sc = (MODE == 2) ? scale[r] : 0.f;
        #pragma unroll
        for (int j = 0; j < 4; j++) {
            int c = col0 + tn * 4 + j;
            float v = acc[i][j];
            if (MODE == 1) v = leaky_f(v);
            if (MODE == 2) v = leaky_f(v) * sc + base[r * DD + c];
            C[r * DD + c] = v;
        }
    }
}

// ---------------- attention: atoms attend to residues ----------------
// out_a[a,:] = sum_r sigmoid(aq[a] . rk[r]) * rv[r,:]   (per complex)
__global__ void attn_a_kernel(const int* __restrict__ lig, const int* __restrict__ res) {
    extern __shared__ float sm[];
    float* qs = sm;               // 64 * 256
    float* ks = sm + 64 * DD;     // 16 * 256
    float* vs = ks + 16 * DD;     // 16 * 256

    int b = blockIdx.x;
    int as = lig[2*b], ac = lig[2*b+1];
    int rs = res[2*b], rc = res[2*b+1];
    int tid = threadIdx.x, lane = tid & 31, w = tid >> 5;

    // stage all aq rows of this complex
    for (int i = tid; i < ac * (DD / 4); i += 256)
        ((float4*)qs)[i] = ((const float4*)(gAq + (size_t)as * DD))[i];
    __syncthreads();

    float acc[8][8];
    #pragma unroll
    for (int j = 0; j < 8; j++)
        #pragma unroll
        for (int m = 0; m < 8; m++) acc[j][m] = 0.f;

    for (int r0 = 0; r0 < rc; r0 += 16) {
        int rlim = rc - r0; if (rlim > 16) rlim = 16;
        // stage rk/rv tile
        for (int i = tid; i < rlim * (DD / 4); i += 256) {
            ((float4*)ks)[i] = ((const float4*)(gRk + (size_t)(rs + r0) * DD))[i];
            ((float4*)vs)[i] = ((const float4*)(gRv + (size_t)(rs + r0) * DD))[i];
        }
        __syncthreads();

        #pragma unroll
        for (int j = 0; j < 8; j++) {
            int a = w + 8 * j;
            if (a < ac) {
                float qr[8];
                #pragma unroll
                for (int m = 0; m < 8; m++) qr[m] = qs[a * DD + lane + 32 * m];
                #pragma unroll 4
                for (int rr = 0; rr < rlim; rr++) {
                    float s = 0.f;
                    #pragma unroll
                    for (int m = 0; m < 8; m++) s += qr[m] * ks[rr * DD + lane + 32 * m];
                    #pragma unroll
                    for (int o = 16; o > 0; o >>= 1) s += __shfl_xor_sync(0xffffffffu, s, o);
                    float sig = sigmoid_f(s);
                    #pragma unroll
                    for (int m = 0; m < 8; m++) acc[j][m] += sig * vs[rr * DD + lane + 32 * m];
                }
            }
        }
        __syncthreads();
    }

    #pragma unroll
    for (int j = 0; j < 8; j++) {
        int a = w + 8 * j;
        if (a < ac)
            #pragma unroll
            for (int m = 0; m < 8; m++)
                gTA[(size_t)(as + a) * DD + lane + 32 * m] = acc[j][m];
    }
}

// ---------------- attention: residues attend to atoms ----------------
// out_r[r,:] = sum_a sigmoid(rq[r] . ak[a]) * av[a,:]   (per complex)
__global__ void attn_r_kernel(const int* __restrict__ lig, const int* __restrict__ res) {
    extern __shared__ float sm[];
    float* aks = sm;              // 64 * 256
    float* avs = sm + 64 * DD;    // 64 * 256

    int b = blockIdx.x;
    int as = lig[2*b], ac = lig[2*b+1];
    int rs = res[2*b], rc = res[2*b+1];
    int tid = threadIdx.x, lane = tid & 31, w = tid >> 5;

    for (int i = tid; i < ac * (DD / 4); i += 256) {
        ((float4*)aks)[i] = ((const float4*)(gAk + (size_t)as * DD))[i];
        ((float4*)avs)[i] = ((const float4*)(gAv + (size_t)as * DD))[i];
    }
    __syncthreads();

    for (int r = w; r < rc; r += 8) {
        float qr[8];
        #pragma unroll
        for (int m = 0; m < 8; m++) qr[m] = gRq[(size_t)(rs + r) * DD + lane + 32 * m];
        float acc[8];
        #pragma unroll
        for (int m = 0; m < 8; m++) acc[m] = 0.f;

        for (int a = 0; a < ac; a++) {
            float s = 0.f;
            #pragma unroll
            for (int m = 0; m < 8; m++) s += qr[m] * aks[a * DD + lane + 32 * m];
            #pragma unroll
            for (int o = 16; o > 0; o >>= 1) s += __shfl_xor_sync(0xffffffffu, s, o);
            float sig = sigmoid_f(s);
            #pragma unroll
            for (int m = 0; m < 8; m++) acc[m] += sig * avs[a * DD + lane + 32 * m];
        }
        #pragma unroll
        for (int m = 0; m < 8; m++)
            gTR[(size_t)(rs + r) * DD + lane + 32 * m] = acc[m];
    }
}

// ---------------- final output: concat(A_flat, R_flat) ----------------
__global__ void copy_out_kernel(float* __restrict__ out, int nA, int nR) {
    size_t na4 = (size_t)nA * DD / 4;
    size_t tot = (size_t)(nA + nR) * DD / 4;
    const float4* a4 = (const float4*)gA;
    const float4* r4 = (const float4*)gR;
    for (size_t i = blockIdx.x * (size_t)blockDim.x + threadIdx.x; i < tot;
         i += (size_t)gridDim.x * blockDim.x) {
        ((float4*)out)[i] = (i < na4) ? a4[i] : r4[i - na4];
    }
}

// ---------------- host launch ----------------
extern "C" void kernel_launch(void* const* d_in, const int* in_sizes, int n_in,
                              void* d_out, int out_size) {
    const float* fatoms = (const float*)d_in[0];
    const float* fres   = (const float*)d_in[1];
    const float* W_lig  = (const float*)d_in[2];
    const float* W_res  = (const float*)d_in[3];
    const float* WQl = (const float*)d_in[4];
    const float* WKl = (const float*)d_in[5];
    const float* WVl = (const float*)d_in[6];
    const float* WOl = (const float*)d_in[7];
    const float* WQr = (const float*)d_in[8];
    const float* WKr = (const float*)d_in[9];
    const float* WVr = (const float*)d_in[10];
    const float* WOr = (const float*)d_in[11];
    const int* lig = (const int*)d_in[12];
    const int* res = (const int*)d_in[13];

    int nA = in_sizes[0] / DD;
    int nR = in_sizes[1] / DD;

    // device pointers to globals (queried each call; cheap, capture-safe)
    float *pA, *pR, *pAq, *pAk, *pAv, *pRq, *pRk, *pRv, *pTA, *pTR, *pInvA, *pInvR;
    cudaGetSymbolAddress((void**)&pA,  gA);
    cudaGetSymbolAddress((void**)&pR,  gR);
    cudaGetSymbolAddress((void**)&pAq, gAq);
    cudaGetSymbolAddress((void**)&pAk, gAk);
    cudaGetSymbolAddress((void**)&pAv, gAv);
    cudaGetSymbolAddress((void**)&pRq, gRq);
    cudaGetSymbolAddress((void**)&pRk, gRk);
    cudaGetSymbolAddress((void**)&pRv, gRv);
    cudaGetSymbolAddress((void**)&pTA, gTA);
    cudaGetSymbolAddress((void**)&pTR, gTR);
    cudaGetSymbolAddress((void**)&pInvA, gInvA);
    cudaGetSymbolAddress((void**)&pInvR, gInvR);

    const int SMEM_A = (64 * DD + 2 * 16 * DD) * 4;   // 96 KB
    const int SMEM_R = (2 * 64 * DD) * 4;             // 128 KB
    cudaFuncSetAttribute(attn_a_kernel, cudaFuncAttributeMaxDynamicSharedMemorySize, SMEM_A);
    cudaFuncSetAttribute(attn_r_kernel, cudaFuncAttributeMaxDynamicSharedMemorySize, SMEM_R);

    dim3 gridA((nA + 63) / 64, 4);
    dim3 gridR((nR + 63) / 64, 4);

    fill_inv_kernel<<<256, 256>>>(lig, res);

    // input transforms: A0 = leaky(fatoms @ W_lig_t), R0 = leaky(fresidues @ W_res_t)
    gemm64_kernel<1><<<gridA, 256>>>(fatoms, W_lig, pA, nA, nullptr, nullptr);
    gemm64_kernel<1><<<gridR, 256>>>(fres,   W_res, pR, nR, nullptr, nullptr);

    for (int it = 0; it < 3; it++) {
        // projections (all from pre-update state)
        gemm64_kernel<0><<<gridA, 256>>>(pA, WQl, pAq, nA, nullptr, nullptr);
        gemm64_kernel<0><<<gridA, 256>>>(pA, WKl, pAk, nA, nullptr, nullptr);
        gemm64_kernel<0><<<gridA, 256>>>(pA, WVl, pAv, nA, nullptr, nullptr);
        gemm64_kernel<0><<<gridR, 256>>>(pR, WQr, pRq, nR, nullptr, nullptr);
        gemm64_kernel<0><<<gridR, 256>>>(pR, WKr, pRk, nR, nullptr, nullptr);
        gemm64_kernel<0><<<gridR, 256>>>(pR, WVr, pRv, nR, nullptr, nullptr);

        // bidirectional sigmoid attention (ragged, per-complex blocks)
        attn_a_kernel<<<256, 256, SMEM_A>>>(lig, res);
        attn_r_kernel<<<256, 256, SMEM_R>>>(lig, res);

        // updates: A = leaky(tmpA @ WOl) / r_cnt + A ; R = leaky(tmpR @ WOr) / a_cnt + R
        gemm64_kernel<2><<<gridA, 256>>>(pTA, WOl, pA, nA, pInvA, pA);
        gemm64_kernel<2><<<gridR, 256>>>(pTR, WOr, pR, nR, pInvR, pR);
    }

    copy_out_kernel<<<1024, 256>>>((float*)d_out, nA, nR);
}

// round 2
// speedup vs baseline: 1.2652x; 1.2652x over previous
#include <cuda_runtime.h>
#include <cstdint>

#define DD 256
#define NA_MAX (64*256)
#define NR_MAX (512*256)

// ---------------- scratch state (device globals; no allocation) ----------------
__device__ __align__(16) float gA [NA_MAX*DD];
__device__ __align__(16) float gR [NR_MAX*DD];
__device__ __align__(16) float gAq[NA_MAX*DD];
__device__ __align__(16) float gAk[NA_MAX*DD];
__device__ __align__(16) float gAv[NA_MAX*DD];
__device__ __align__(16) float gRq[NR_MAX*DD];
__device__ __align__(16) float gRk[NR_MAX*DD];
__device__ __align__(16) float gRv[NR_MAX*DD];
__device__ __align__(16) float gTA[NA_MAX*DD];
__device__ __align__(16) float gTR[NR_MAX*DD];
__device__ float gInvA[NA_MAX];
__device__ float gInvR[NR_MAX];

__device__ __forceinline__ float leaky_f(float x) { return x >= 0.f ? x : 0.1f * x; }
__device__ __forceinline__ float sigmoid_f(float x) {
    return __fdividef(1.f, 1.f + __expf(-x));
}

__device__ __forceinline__ void split_tf32(float x, float& hi, float& lo) {
    uint32_t u;
    asm("cvt.rna.tf32.f32 %0, %1;" : "=r"(u) : "f"(x));
    hi = __uint_as_float(u);
    float r = x - hi;
    uint32_t v;
    asm("cvt.rna.tf32.f32 %0, %1;" : "=r"(v) : "f"(r));
    lo = __uint_as_float(v);
}

__device__ __forceinline__ void mma_tf32(float* d, const uint32_t* a, const uint32_t* b) {
    asm volatile(
        "mma.sync.aligned.m16n8k8.row.col.f32.tf32.tf32.f32 "
        "{%0,%1,%2,%3}, {%4,%5,%6,%7}, {%8,%9}, {%0,%1,%2,%3};\n"
        : "+f"(d[0]), "+f"(d[1]), "+f"(d[2]), "+f"(d[3])
        : "r"(a[0]), "r"(a[1]), "r"(a[2]), "r"(a[3]), "r"(b[0]), "r"(b[1]));
}

// ---------------- per-row 1/count scales ----------------
__global__ void fill_inv_kernel(const int* __restrict__ lig, const int* __restrict__ res) {
    int b = blockIdx.x;
    int as = lig[2*b], ac = lig[2*b+1];
    int rs = res[2*b], rc = res[2*b+1];
    float ia = 1.f / (float)rc;
    float ir = 1.f / (float)ac;
    for (int i = threadIdx.x; i < ac; i += blockDim.x) gInvA[as + i] = ia;
    for (int i = threadIdx.x; i < rc; i += blockDim.x) gInvR[rs + i] = ir;
}

// ---------------- 3xTF32 tensor-core GEMM: C[M,256] = X[M,256] @ W[256,256] ----------------
// MODE 0: C = XW ; MODE 1: C = leaky(XW) ; MODE 2: C = leaky(XW)*scale[r] + base[r,c]
// Tile: 128(M) x 64(N) per 256-thread CTA, BK=32. 8 warps as 4(m) x 2(n), warp tile 32x32.
#define SA_STR 36   // A smem row stride (floats): conflict-free m16n8k8 A-frag loads
#define SB_STR 72   // B smem k-row stride (floats): conflict-free B-frag loads
#define GEMM_SMEM ((2*128*SA_STR + 2*32*SB_STR) * 4)

template <int MODE>
__global__ void gemm_tf32_kernel(const float* __restrict__ X, const float* __restrict__ W,
                                 float* __restrict__ C, int M,
                                 const float* __restrict__ scale, const float* __restrict__ base)
{
    extern __shared__ float smf[];
    float* sAh = smf;                    // [128][SA_STR] row-major (m, k)
    float* sAl = sAh + 128 * SA_STR;
    float* sBh = sAl + 128 * SA_STR;     // [32][SB_STR] k-major (k, n)
    float* sBl = sBh + 32 * SB_STR;

    const int row0 = blockIdx.x * 128;
    const int col0 = blockIdx.y * 64;
    const int tid = threadIdx.x, lane = tid & 31, warp = tid >> 5;
    const int wm = warp >> 1, wn = warp & 1;
    const int lq = lane >> 2, lr = lane & 3;

    float acc[2][4][4] = {};

    for (int k0 = 0; k0 < DD; k0 += 32) {
        // ---- stage A tile (128 x 32), split hi/lo ----
        #pragma unroll
        for (int i = 0; i < 4; i++) {
            int idx = tid + 256 * i;
            int row = idx >> 3, kq = idx & 7;
            float4 v = make_float4(0.f, 0.f, 0.f, 0.f);
            if (row0 + row < M)
                v = *(const float4*)(X + (size_t)(row0 + row) * DD + k0 + kq * 4);
            float4 h, l;
            split_tf32(v.x, h.x, l.x); split_tf32(v.y, h.y, l.y);
            split_tf32(v.z, h.z, l.z); split_tf32(v.w, h.w, l.w);
            *(float4*)&sAh[row * SA_STR + kq * 4] = h;
            *(float4*)&sAl[row * SA_STR + kq * 4] = l;
        }
        // ---- stage B tile (32 x 64), split hi/lo ----
        #pragma unroll
        for (int i = 0; i < 2; i++) {
            int idx = tid + 256 * i;
            int k = idx >> 4, cq = idx & 15;
            float4 v = *(const float4*)(W + (size_t)(k0 + k) * DD + col0 + cq * 4);
            float4 h, l;
            split_tf32(v.x, h.x, l.x); split_tf32(v.y, h.y, l.y);
            split_tf32(v.z, h.z, l.z); split_tf32(v.w, h.w, l.w);
            *(float4*)&sBh[k * SB_STR + cq * 4] = h;
            *(float4*)&sBl[k * SB_STR + cq * 4] = l;
        }
        __syncthreads();

        #pragma unroll
        for (int kk = 0; kk < 4; kk++) {
            uint32_t ah[2][4], al[2][4], bh[4][2], bl[4][2];
            #pragma unroll
            for (int mf = 0; mf < 2; mf++) {
                int r = wm * 32 + mf * 16 + lq;
                int k = kk * 8 + lr;
                ah[mf][0] = __float_as_uint(sAh[r * SA_STR + k]);
                ah[mf][1] = __float_as_uint(sAh[(r + 8) * SA_STR + k]);
                ah[mf][2] = __float_as_uint(sAh[r * SA_STR + k + 4]);
                ah[mf][3] = __float_as_uint(sAh[(r + 8) * SA_STR + k + 4]);
                al[mf][0] = __float_as_uint(sAl[r * SA_STR + k]);
                al[mf][1] = __float_as_uint(sAl[(r + 8) * SA_STR + k]);
                al[mf][2] = __float_as_uint(sAl[r * SA_STR + k + 4]);
                al[mf][3] = __float_as_uint(sAl[(r + 8) * SA_STR + k + 4]);
            }
            #pragma unroll
            for (int nf = 0; nf < 4; nf++) {
                int n = wn * 32 + nf * 8 + lq;
                int k = kk * 8 + lr;
                bh[nf][0] = __float_as_uint(sBh[k * SB_STR + n]);
                bh[nf][1] = __float_as_uint(sBh[(k + 4) * SB_STR + n]);
                bl[nf][0] = __float_as_uint(sBl[k * SB_STR + n]);
                bl[nf][1] = __float_as_uint(sBl[(k + 4) * SB_STR + n]);
            }
            #pragma unroll
            for (int mf = 0; mf < 2; mf++)
                #pragma unroll
                for (int nf = 0; nf < 4; nf++) {
                    mma_tf32(acc[mf][nf], al[mf], bh[nf]);
                    mma_tf32(acc[mf][nf], ah[mf], bl[nf]);
                    mma_tf32(acc[mf][nf], ah[mf], bh[nf]);
                }
        }
        __syncthreads();
    }

    // ---- epilogue ----
    #pragma unroll
    for (int mf = 0; mf < 2; mf++) {
        #pragma unroll
        for (int i = 0; i < 4; i++) {
            int r = row0 + wm * 32 + mf * 16 + lq + ((i >= 2) ? 8 : 0);
            if (r >= M) continue;
            float sc = (MODE == 2) ? scale[r] : 0.f;
            #pragma unroll
            for (int nf = 0; nf < 4; nf++) {
                int c = col0 + wn * 32 + nf * 8 + lr * 2 + (i & 1);
                float v = acc[mf][nf][i];
                if (MODE == 1) v = leaky_f(v);
                if (MODE == 2) v = leaky_f(v) * sc + base[(size_t)r * DD + c];
                C[(size_t)r * DD + c] = v;
            }
        }
    }
}

// ---------------- attention: atoms attend to residues ----------------
__global__ void attn_a_kernel(const int* __restrict__ lig, const int* __restrict__ res) {
    extern __shared__ float sm[];
    float* qs = sm;               // 64 * 256
    float* ks = sm + 64 * DD;     // 16 * 256
    float* vs = ks + 16 * DD;     // 16 * 256

    int b = blockIdx.x;
    int as = lig[2*b], ac = lig[2*b+1];
    int rs = res[2*b], rc = res[2*b+1];
    int tid = threadIdx.x, lane = tid & 31, w = tid >> 5;

    for (int i = tid; i < ac * (DD / 4); i += 256)
        ((float4*)qs)[i] = ((const float4*)(gAq + (size_t)as * DD))[i];
    __syncthreads();

    float acc[8][8];
    #pragma unroll
    for (int j = 0; j < 8; j++)
        #pragma unroll
        for (int m = 0; m < 8; m++) acc[j][m] = 0.f;

    for (int r0 = 0; r0 < rc; r0 += 16) {
        int rlim = rc - r0; if (rlim > 16) rlim = 16;
        for (int i = tid; i < rlim * (DD / 4); i += 256) {
            ((float4*)ks)[i] = ((const float4*)(gRk + (size_t)(rs + r0) * DD))[i];
            ((float4*)vs)[i] = ((const float4*)(gRv + (size_t)(rs + r0) * DD))[i];
        }
        __syncthreads();

        #pragma unroll
        for (int j = 0; j < 8; j++) {
            int a = w + 8 * j;
            if (a < ac) {
                float qr[8];
                #pragma unroll
                for (int m = 0; m < 8; m++) qr[m] = qs[a * DD + lane + 32 * m];
                #pragma unroll 4
                for (int rr = 0; rr < rlim; rr++) {
                    float s = 0.f;
                    #pragma unroll
                    for (int m = 0; m < 8; m++) s += qr[m] * ks[rr * DD + lane + 32 * m];
                    #pragma unroll
                    for (int o = 16; o > 0; o >>= 1) s += __shfl_xor_sync(0xffffffffu, s, o);
                    float sig = sigmoid_f(s);
                    #pragma unroll
                    for (int m = 0; m < 8; m++) acc[j][m] += sig * vs[rr * DD + lane + 32 * m];
                }
            }
        }
        __syncthreads();
    }

    #pragma unroll
    for (int j = 0; j < 8; j++) {
        int a = w + 8 * j;
        if (a < ac)
            #pragma unroll
            for (int m = 0; m < 8; m++)
                gTA[(size_t)(as + a) * DD + lane + 32 * m] = acc[j][m];
    }
}

// ---------------- attention: residues attend to atoms (chunked for balance) ----------------
__global__ void attn_r_kernel(const int* __restrict__ lig, const int* __restrict__ res) {
    extern __shared__ float sm[];
    float* aks = sm;              // 64 * 256
    float* avs = sm + 64 * DD;    // 64 * 256

    int b = blockIdx.x;
    int as = lig[2*b], ac = lig[2*b+1];
    int rs = res[2*b], rc = res[2*b+1];
    int chunk = blockIdx.y;
    int rbeg = chunk * 128;
    if (rbeg >= rc) return;
    int rend = rbeg + 128; if (rend > rc) rend = rc;

    int tid = threadIdx.x, lane = tid & 31, w = tid >> 5;

    for (int i = tid; i < ac * (DD / 4); i += 256) {
        ((float4*)aks)[i] = ((const float4*)(gAk + (size_t)as * DD))[i];
        ((float4*)avs)[i] = ((const float4*)(gAv + (size_t)as * DD))[i];
    }
    __syncthreads();

    for (int r = rbeg + w; r < rend; r += 8) {
        float qr[8];
        #pragma unroll
        for (int m = 0; m < 8; m++) qr[m] = gRq[(size_t)(rs + r) * DD + lane + 32 * m];
        float acc[8];
        #pragma unroll
        for (int m = 0; m < 8; m++) acc[m] = 0.f;

        for (int a = 0; a < ac; a++) {
            float s = 0.f;
            #pragma unroll
            for (int m = 0; m < 8; m++) s += qr[m] * aks[a * DD + lane + 32 * m];
            #pragma unroll
            for (int o = 16; o > 0; o >>= 1) s += __shfl_xor_sync(0xffffffffu, s, o);
            float sig = sigmoid_f(s);
            #pragma unroll
            for (int m = 0; m < 8; m++) acc[m] += sig * avs[a * DD + lane + 32 * m];
        }
        #pragma unroll
        for (int m = 0; m < 8; m++)
            gTR[(size_t)(rs + r) * DD + lane + 32 * m] = acc[m];
    }
}

// ---------------- final output: concat(A_flat, R_flat) ----------------
__global__ void copy_out_kernel(float* __restrict__ out, int nA, int nR) {
    size_t na4 = (size_t)nA * DD / 4;
    size_t tot = (size_t)(nA + nR) * DD / 4;
    const float4* a4 = (const float4*)gA;
    const float4* r4 = (const float4*)gR;
    for (size_t i = blockIdx.x * (size_t)blockDim.x + threadIdx.x; i < tot;
         i += (size_t)gridDim.x * blockDim.x) {
        ((float4*)out)[i] = (i < na4) ? a4[i] : r4[i - na4];
    }
}

// ---------------- host launch ----------------
extern "C" void kernel_launch(void* const* d_in, const int* in_sizes, int n_in,
                              void* d_out, int out_size) {
    const float* fatoms = (const float*)d_in[0];
    const float* fres   = (const float*)d_in[1];
    const float* W_lig  = (const float*)d_in[2];
    const float* W_res  = (const float*)d_in[3];
    const float* WQl = (const float*)d_in[4];
    const float* WKl = (const float*)d_in[5];
    const float* WVl = (const float*)d_in[6];
    const float* WOl = (const float*)d_in[7];
    const float* WQr = (const float*)d_in[8];
    const float* WKr = (const float*)d_in[9];
    const float* WVr = (const float*)d_in[10];
    const float* WOr = (const float*)d_in[11];
    const int* lig = (const int*)d_in[12];
    const int* res = (const int*)d_in[13];

    int nA = in_sizes[0] / DD;
    int nR = in_sizes[1] / DD;

    float *pA, *pR, *pAq, *pAk, *pAv, *pRq, *pRk, *pRv, *pTA, *pTR, *pInvA, *pInvR;
    cudaGetSymbolAddress((void**)&pA,  gA);
    cudaGetSymbolAddress((void**)&pR,  gR);
    cudaGetSymbolAddress((void**)&pAq, gAq);
    cudaGetSymbolAddress((void**)&pAk, gAk);
    cudaGetSymbolAddress((void**)&pAv, gAv);
    cudaGetSymbolAddress((void**)&pRq, gRq);
    cudaGetSymbolAddress((void**)&pRk, gRk);
    cudaGetSymbolAddress((void**)&pRv, gRv);
    cudaGetSymbolAddress((void**)&pTA, gTA);
    cudaGetSymbolAddress((void**)&pTR, gTR);
    cudaGetSymbolAddress((void**)&pInvA, gInvA);
    cudaGetSymbolAddress((void**)&pInvR, gInvR);

    const int SMEM_A = (64 * DD + 2 * 16 * DD) * 4;   // 96 KB
    const int SMEM_R = (2 * 64 * DD) * 4;             // 128 KB
    cudaFuncSetAttribute(attn_a_kernel, cudaFuncAttributeMaxDynamicSharedMemorySize, SMEM_A);
    cudaFuncSetAttribute(attn_r_kernel, cudaFuncAttributeMaxDynamicSharedMemorySize, SMEM_R);
    cudaFuncSetAttribute(gemm_tf32_kernel<0>, cudaFuncAttributeMaxDynamicSharedMemorySize, GEMM_SMEM);
    cudaFuncSetAttribute(gemm_tf32_kernel<1>, cudaFuncAttributeMaxDynamicSharedMemorySize, GEMM_SMEM);
    cudaFuncSetAttribute(gemm_tf32_kernel<2>, cudaFuncAttributeMaxDynamicSharedMemorySize, GEMM_SMEM);

    dim3 gridA((nA + 127) / 128, 4);
    dim3 gridR((nR + 127) / 128, 4);

    fill_inv_kernel<<<256, 256>>>(lig, res);

    gemm_tf32_kernel<1><<<gridA, 256, GEMM_SMEM>>>(fatoms, W_lig, pA, nA, nullptr, nullptr);
    gemm_tf32_kernel<1><<<gridR, 256, GEMM_SMEM>>>(fres,   W_res, pR, nR, nullptr, nullptr);

    for (int it = 0; it < 3; it++) {
        gemm_tf32_kernel<0><<<gridA, 256, GEMM_SMEM>>>(pA, WQl, pAq, nA, nullptr, nullptr);
        gemm_tf32_kernel<0><<<gridA, 256, GEMM_SMEM>>>(pA, WKl, pAk, nA, nullptr, nullptr);
        gemm_tf32_kernel<0><<<gridA, 256, GEMM_SMEM>>>(pA, WVl, pAv, nA, nullptr, nullptr);
        gemm_tf32_kernel<0><<<gridR, 256, GEMM_SMEM>>>(pR, WQr, pRq, nR, nullptr, nullptr);
        gemm_tf32_kernel<0><<<gridR, 256, GEMM_SMEM>>>(pR, WKr, pRk, nR, nullptr, nullptr);
        gemm_tf32_kernel<0><<<gridR, 256, GEMM_SMEM>>>(pR, WVr, pRv, nR, nullptr, nullptr);

        attn_a_kernel<<<256, 256, SMEM_A>>>(lig, res);
        attn_r_kernel<<<dim3(256, 4), 256, SMEM_R>>>(lig, res);

        gemm_tf32_kernel<2><<<gridA, 256, GEMM_SMEM>>>(pTA, WOl, pA, nA, pInvA, pA);
        gemm_tf32_kernel<2><<<gridR, 256, GEMM_SMEM>>>(pTR, WOr, pR, nR, pInvR, pR);
    }

    copy_out_kernel<<<1024, 256>>>((float*)d_out, nA, nR);
}

// round 3
// speedup vs baseline: 2.1905x; 1.7313x over previous
#include <cuda_runtime.h>
#include <cstdint>

#define DD 256
#define NA_MAX (64*256)
#define NR_MAX (512*256)

// ---------------- scratch state (device globals; no allocation) ----------------
__device__ __align__(16) float gA [NA_MAX*DD];
__device__ __align__(16) float gR [NR_MAX*DD];
__device__ __align__(16) float gAq[NA_MAX*DD];
__device__ __align__(16) float gAk[NA_MAX*DD];
__device__ __align__(16) float gAv[NA_MAX*DD];
__device__ __align__(16) float gRq[NR_MAX*DD];
__device__ __align__(16) float gRk[NR_MAX*DD];
__device__ __align__(16) float gRv[NR_MAX*DD];
__device__ __align__(16) float gTA[NA_MAX*DD];
__device__ __align__(16) float gTR[NR_MAX*DD];
__device__ float gInvA[NA_MAX];
__device__ float gInvR[NR_MAX];

__device__ __forceinline__ float leaky_f(float x) { return x >= 0.f ? x : 0.1f * x; }
__device__ __forceinline__ float sigmoid_f(float x) {
    return __fdividef(1.f, 1.f + __expf(-x));
}
__device__ __forceinline__ float to_tf32(float x) {
    uint32_t u;
    asm("cvt.rna.tf32.f32 %0, %1;" : "=r"(u) : "f"(x));
    return __uint_as_float(u);
}
__device__ __forceinline__ void split_tf32(float x, float& hi, float& lo) {
    uint32_t u;
    asm("cvt.rna.tf32.f32 %0, %1;" : "=r"(u) : "f"(x));
    hi = __uint_as_float(u);
    float r = x - hi;
    uint32_t v;
    asm("cvt.rna.tf32.f32 %0, %1;" : "=r"(v) : "f"(r));
    lo = __uint_as_float(v);
}
__device__ __forceinline__ void mma_tf32(float* d, const uint32_t* a, const uint32_t* b) {
    asm volatile(
        "mma.sync.aligned.m16n8k8.row.col.f32.tf32.tf32.f32 "
        "{%0,%1,%2,%3}, {%4,%5,%6,%7}, {%8,%9}, {%0,%1,%2,%3};\n"
        : "+f"(d[0]), "+f"(d[1]), "+f"(d[2]), "+f"(d[3])
        : "r"(a[0]), "r"(a[1]), "r"(a[2]), "r"(a[3]), "r"(b[0]), "r"(b[1]));
}

// ---------------- per-row 1/count scales ----------------
__global__ void fill_inv_kernel(const int* __restrict__ lig, const int* __restrict__ res) {
    int b = blockIdx.x;
    int as = lig[2*b], ac = lig[2*b+1];
    int rs = res[2*b], rc = res[2*b+1];
    float ia = 1.f / (float)rc;
    float ir = 1.f / (float)ac;
    for (int i = threadIdx.x; i < ac; i += blockDim.x) gInvA[as + i] = ia;
    for (int i = threadIdx.x; i < rc; i += blockDim.x) gInvR[rs + i] = ir;
}

// ---------------- 3xTF32 tensor-core GEMM: C[M,256] = X[M,256] @ W[256,256] ----------------
// MODE 0: C = XW ; MODE 1: C = leaky(XW) ; MODE 2: C = leaky(XW)*scale[r] + base[r,c]
#define SA_STR 36
#define SB_STR 72
#define GEMM_SMEM ((2*128*SA_STR + 2*32*SB_STR) * 4)

template <int MODE>
__global__ void gemm_tf32_kernel(const float* __restrict__ X, const float* __restrict__ W,
                                 float* __restrict__ C, int M,
                                 const float* __restrict__ scale, const float* __restrict__ base)
{
    extern __shared__ float smf[];
    float* sAh = smf;
    float* sAl = sAh + 128 * SA_STR;
    float* sBh = sAl + 128 * SA_STR;
    float* sBl = sBh + 32 * SB_STR;

    const int row0 = blockIdx.x * 128;
    const int col0 = blockIdx.y * 64;
    const int tid = threadIdx.x, lane = tid & 31, warp = tid >> 5;
    const int wm = warp >> 1, wn = warp & 1;
    const int lq = lane >> 2, lr = lane & 3;

    float acc[2][4][4] = {};

    for (int k0 = 0; k0 < DD; k0 += 32) {
        #pragma unroll
        for (int i = 0; i < 4; i++) {
            int idx = tid + 256 * i;
            int row = idx >> 3, kq = idx & 7;
            float4 v = make_float4(0.f, 0.f, 0.f, 0.f);
            if (row0 + row < M)
                v = *(const float4*)(X + (size_t)(row0 + row) * DD + k0 + kq * 4);
            float4 h, l;
            split_tf32(v.x, h.x, l.x); split_tf32(v.y, h.y, l.y);
            split_tf32(v.z, h.z, l.z); split_tf32(v.w, h.w, l.w);
            *(float4*)&sAh[row * SA_STR + kq * 4] = h;
            *(float4*)&sAl[row * SA_STR + kq * 4] = l;
        }
        #pragma unroll
        for (int i = 0; i < 2; i++) {
            int idx = tid + 256 * i;
            int k = idx >> 4, cq = idx & 15;
            float4 v = *(const float4*)(W + (size_t)(k0 + k) * DD + col0 + cq * 4);
            float4 h, l;
            split_tf32(v.x, h.x, l.x); split_tf32(v.y, h.y, l.y);
            split_tf32(v.z, h.z, l.z); split_tf32(v.w, h.w, l.w);
            *(float4*)&sBh[k * SB_STR + cq * 4] = h;
            *(float4*)&sBl[k * SB_STR + cq * 4] = l;
        }
        __syncthreads();

        #pragma unroll
        for (int kk = 0; kk < 4; kk++) {
            uint32_t ah[2][4], al[2][4], bh[4][2], bl[4][2];
            #pragma unroll
            for (int mf = 0; mf < 2; mf++) {
                int r = wm * 32 + mf * 16 + lq;
                int k = kk * 8 + lr;
                ah[mf][0] = __float_as_uint(sAh[r * SA_STR + k]);
                ah[mf][1] = __float_as_uint(sAh[(r + 8) * SA_STR + k]);
                ah[mf][2] = __float_as_uint(sAh[r * SA_STR + k + 4]);
                ah[mf][3] = __float_as_uint(sAh[(r + 8) * SA_STR + k + 4]);
                al[mf][0] = __float_as_uint(sAl[r * SA_STR + k]);
                al[mf][1] = __float_as_uint(sAl[(r + 8) * SA_STR + k]);
                al[mf][2] = __float_as_uint(sAl[r * SA_STR + k + 4]);
                al[mf][3] = __float_as_uint(sAl[(r + 8) * SA_STR + k + 4]);
            }
            #pragma unroll
            for (int nf = 0; nf < 4; nf++) {
                int n = wn * 32 + nf * 8 + lq;
                int k = kk * 8 + lr;
                bh[nf][0] = __float_as_uint(sBh[k * SB_STR + n]);
                bh[nf][1] = __float_as_uint(sBh[(k + 4) * SB_STR + n]);
                bl[nf][0] = __float_as_uint(sBl[k * SB_STR + n]);
                bl[nf][1] = __float_as_uint(sBl[(k + 4) * SB_STR + n]);
            }
            #pragma unroll
            for (int mf = 0; mf < 2; mf++)
                #pragma unroll
                for (int nf = 0; nf < 4; nf++) {
                    mma_tf32(acc[mf][nf], al[mf], bh[nf]);
                    mma_tf32(acc[mf][nf], ah[mf], bl[nf]);
                    mma_tf32(acc[mf][nf], ah[mf], bh[nf]);
                }
        }
        __syncthreads();
    }

    #pragma unroll
    for (int mf = 0; mf < 2; mf++) {
        #pragma unroll
        for (int i = 0; i < 4; i++) {
            int r = row0 + wm * 32 + mf * 16 + lq + ((i >= 2) ? 8 : 0);
            if (r >= M) continue;
            float sc = (MODE == 2) ? scale[r] : 0.f;
            #pragma unroll
            for (int nf = 0; nf < 4; nf++) {
                int c = col0 + wn * 32 + nf * 8 + lr * 2 + (i & 1);
                float v = acc[mf][nf][i];
                if (MODE == 1) v = leaky_f(v);
                if (MODE == 2) v = leaky_f(v) * sc + base[(size_t)r * DD + c];
                C[(size_t)r * DD + c] = v;
            }
        }
    }
}

// ---------------- mma-based sigmoid attention (unified, ragged) ----------------
// Per block: 64-row query chunk of complex b. O[q,:] = sum_kv sigmoid(Q[q].K[kv]) * V[kv,:]
// Phase S: 8 warps as 4(m)x2(n) compute 64x32 score tile (K=256, tf32 mma).
// Phase PV: 8 warps split 256 feat cols (32 each); O += S @ V, K=32 per tile.
#define QSTR 264           // 256 + 8 pad (floats)
#define SSTR 40            // 32 + 8 pad
#define ATT_SMEM ((64*QSTR + 2*32*QSTR + 64*SSTR) * 4)

__global__ void attn_mma_kernel(const float* __restrict__ Q, const float* __restrict__ K,
                                const float* __restrict__ V, float* __restrict__ O,
                                const int* __restrict__ scQ, const int* __restrict__ scKV)
{
    extern __shared__ float smf[];
    float* sQ = smf;                    // [64][QSTR]
    float* sK = sQ + 64 * QSTR;         // [32][QSTR]
    float* sV = sK + 32 * QSTR;         // [32][QSTR]
    float* sS = sV + 32 * QSTR;         // [64][SSTR]

    const int b = blockIdx.x;
    const int qs0 = scQ[2*b], qc = scQ[2*b+1];
    const int kv0 = scKV[2*b], kvc = scKV[2*b+1];
    const int qbeg = blockIdx.y * 64;
    if (qbeg >= qc) return;
    const int qcnt = (qc - qbeg < 64) ? (qc - qbeg) : 64;

    const int tid = threadIdx.x, lane = tid & 31, warp = tid >> 5;
    const int lq = lane >> 2, lr = lane & 3;
    const float* Qbase = Q + (size_t)(qs0 + qbeg) * DD;
    const float* Kbase = K + (size_t)kv0 * DD;
    const float* Vbase = V + (size_t)kv0 * DD;

    // ---- stage Q chunk (tf32) ----
    #pragma unroll
    for (int i = 0; i < 16; i++) {
        int idx = tid + 256 * i;
        int row = idx >> 6, q4 = idx & 63;
        float4 v = make_float4(0.f, 0.f, 0.f, 0.f);
        if (row < qcnt) v = *(const float4*)(Qbase + row * DD + q4 * 4);
        v.x = to_tf32(v.x); v.y = to_tf32(v.y); v.z = to_tf32(v.z); v.w = to_tf32(v.w);
        *(float4*)&sQ[row * QSTR + q4 * 4] = v;
    }

    float o[4][4][4] = {};   // PV accumulators: 4 m-frags x 4 n-frags

    for (int t0 = 0; t0 < kvc; t0 += 32) {
        int klim = kvc - t0; if (klim > 32) klim = 32;
        __syncthreads();
        // ---- stage K/V tile (tf32) ----
        #pragma unroll
        for (int i = 0; i < 8; i++) {
            int idx = tid + 256 * i;
            int row = idx >> 6, q4 = idx & 63;
            float4 kv4 = make_float4(0.f, 0.f, 0.f, 0.f);
            float4 vv4 = make_float4(0.f, 0.f, 0.f, 0.f);
            if (row < klim) {
                kv4 = *(const float4*)(Kbase + (size_t)(t0 + row) * DD + q4 * 4);
                vv4 = *(const float4*)(Vbase + (size_t)(t0 + row) * DD + q4 * 4);
            }
            kv4.x = to_tf32(kv4.x); kv4.y = to_tf32(kv4.y);
            kv4.z = to_tf32(kv4.z); kv4.w = to_tf32(kv4.w);
            vv4.x = to_tf32(vv4.x); vv4.y = to_tf32(vv4.y);
            vv4.z = to_tf32(vv4.z); vv4.w = to_tf32(vv4.w);
            *(float4*)&sK[row * QSTR + q4 * 4] = kv4;
            *(float4*)&sV[row * QSTR + q4 * 4] = vv4;
        }
        __syncthreads();

        // ---- phase S: scores 64x32, K=256 ----
        {
            const int wm = warp >> 1, wn = warp & 1;
            const int m0 = wm * 16, n0 = wn * 16;
            float s[2][4] = {};
            #pragma unroll 4
            for (int kk = 0; kk < 32; kk++) {
                uint32_t a[4], bb[2][2];
                const float* qp = sQ + (m0 + lq) * QSTR + kk * 8 + lr;
                a[0] = __float_as_uint(qp[0]);
                a[1] = __float_as_uint(qp[8 * QSTR]);
                a[2] = __float_as_uint(qp[4]);
                a[3] = __float_as_uint(qp[8 * QSTR + 4]);
                #pragma unroll
                for (int nf = 0; nf < 2; nf++) {
                    const float* kp = sK + (n0 + nf * 8 + lq) * QSTR + kk * 8 + lr;
                    bb[nf][0] = __float_as_uint(kp[0]);
                    bb[nf][1] = __float_as_uint(kp[4]);
                }
                mma_tf32(s[0], a, bb[0]);
                mma_tf32(s[1], a, bb[1]);
            }
            // sigmoid + ragged mask + tf32 store
            #pragma unroll
            for (int nf = 0; nf < 2; nf++)
                #pragma unroll
                for (int e = 0; e < 4; e++) {
                    int row = m0 + lq + ((e >= 2) ? 8 : 0);
                    int col = n0 + nf * 8 + lr * 2 + (e & 1);
                    float v = (col < klim) ? sigmoid_f(s[nf][e]) : 0.f;
                    sS[row * SSTR + col] = to_tf32(v);
                }
        }
        __syncthreads();

        // ---- phase PV: O += S @ V, each warp owns 32 feat cols ----
        {
            const int n0 = warp * 32;
            #pragma unroll
            for (int ks = 0; ks < 4; ks++) {
                uint32_t a[4][4], bb[4][2];
                #pragma unroll
                for (int mf = 0; mf < 4; mf++) {
                    const float* sp = sS + (mf * 16 + lq) * SSTR + ks * 8 + lr;
                    a[mf][0] = __float_as_uint(sp[0]);
                    a[mf][1] = __float_as_uint(sp[8 * SSTR]);
                    a[mf][2] = __float_as_uint(sp[4]);
                    a[mf][3] = __float_as_uint(sp[8 * SSTR + 4]);
                }
                #pragma unroll
                for (int nf = 0; nf < 4; nf++) {
                    const float* vp = sV + (ks * 8 + lr) * QSTR + n0 + nf * 8 + lq;
                    bb[nf][0] = __float_as_uint(vp[0]);
                    bb[nf][1] = __float_as_uint(vp[4 * QSTR]);
                }
                #pragma unroll
                for (int mf = 0; mf < 4; mf++)
                    #pragma unroll
                    for (int nf = 0; nf < 4; nf++)
                        mma_tf32(o[mf][nf], a[mf], bb[nf]);
            }
        }
    }

    // ---- store O ----
    const int n0 = warp * 32;
    float* Obase = O + (size_t)(qs0 + qbeg) * DD;
    #pragma unroll
    for (int mf = 0; mf < 4; mf++)
        #pragma unroll
        for (int e = 0; e < 4; e++) {
            int row = mf * 16 + lq + ((e >= 2) ? 8 : 0);
            if (row >= qcnt) continue;
            #pragma unroll
            for (int nf = 0; nf < 4; nf++) {
                int col = n0 + nf * 8 + lr * 2 + (e & 1);
                Obase[(size_t)row * DD + col] = o[mf][nf][e];
            }
        }
}

// ---------------- final output: concat(A_flat, R_flat) ----------------
__global__ void copy_out_kernel(float* __restrict__ out, int nA, int nR) {
    size_t na4 = (size_t)nA * DD / 4;
    size_t tot = (size_t)(nA + nR) * DD / 4;
    const float4* a4 = (const float4*)gA;
    const float4* r4 = (const float4*)gR;
    for (size_t i = blockIdx.x * (size_t)blockDim.x + threadIdx.x; i < tot;
         i += (size_t)gridDim.x * blockDim.x) {
        ((float4*)out)[i] = (i < na4) ? a4[i] : r4[i - na4];
    }
}

// ---------------- host launch ----------------
extern "C" void kernel_launch(void* const* d_in, const int* in_sizes, int n_in,
                              void* d_out, int out_size) {
    const float* fatoms = (const float*)d_in[0];
    const float* fres   = (const float*)d_in[1];
    const float* W_lig  = (const float*)d_in[2];
    const float* W_res  = (const float*)d_in[3];
    const float* WQl = (const float*)d_in[4];
    const float* WKl = (const float*)d_in[5];
    const float* WVl = (const float*)d_in[6];
    const float* WOl = (const float*)d_in[7];
    const float* WQr = (const float*)d_in[8];
    const float* WKr = (const float*)d_in[9];
    const float* WVr = (const float*)d_in[10];
    const float* WOr = (const float*)d_in[11];
    const int* lig = (const int*)d_in[12];
    const int* res = (const int*)d_in[13];

    int nA = in_sizes[0] / DD;
    int nR = in_sizes[1] / DD;

    float *pA, *pR, *pAq, *pAk, *pAv, *pRq, *pRk, *pRv, *pTA, *pTR, *pInvA, *pInvR;
    cudaGetSymbolAddress((void**)&pA,  gA);
    cudaGetSymbolAddress((void**)&pR,  gR);
    cudaGetSymbolAddress((void**)&pAq, gAq);
    cudaGetSymbolAddress((void**)&pAk, gAk);
    cudaGetSymbolAddress((void**)&pAv, gAv);
    cudaGetSymbolAddress((void**)&pRq, gRq);
    cudaGetSymbolAddress((void**)&pRk, gRk);
    cudaGetSymbolAddress((void**)&pRv, gRv);
    cudaGetSymbolAddress((void**)&pTA, gTA);
    cudaGetSymbolAddress((void**)&pTR, gTR);
    cudaGetSymbolAddress((void**)&pInvA, gInvA);
    cudaGetSymbolAddress((void**)&pInvR, gInvR);

    cudaFuncSetAttribute(gemm_tf32_kernel<0>, cudaFuncAttributeMaxDynamicSharedMemorySize, GEMM_SMEM);
    cudaFuncSetAttribute(gemm_tf32_kernel<1>, cudaFuncAttributeMaxDynamicSharedMemorySize, GEMM_SMEM);
    cudaFuncSetAttribute(gemm_tf32_kernel<2>, cudaFuncAttributeMaxDynamicSharedMemorySize, GEMM_SMEM);
    cudaFuncSetAttribute(attn_mma_kernel, cudaFuncAttributeMaxDynamicSharedMemorySize, ATT_SMEM);

    dim3 gridA((nA + 127) / 128, 4);
    dim3 gridR((nR + 127) / 128, 4);

    fill_inv_kernel<<<256, 256>>>(lig, res);

    gemm_tf32_kernel<1><<<gridA, 256, GEMM_SMEM>>>(fatoms, W_lig, pA, nA, nullptr, nullptr);
    gemm_tf32_kernel<1><<<gridR, 256, GEMM_SMEM>>>(fres,   W_res, pR, nR, nullptr, nullptr);

    for (int it = 0; it < 3; it++) {
        gemm_tf32_kernel<0><<<gridA, 256, GEMM_SMEM>>>(pA, WQl, pAq, nA, nullptr, nullptr);
        gemm_tf32_kernel<0><<<gridA, 256, GEMM_SMEM>>>(pA, WKl, pAk, nA, nullptr, nullptr);
        gemm_tf32_kernel<0><<<gridA, 256, GEMM_SMEM>>>(pA, WVl, pAv, nA, nullptr, nullptr);
        gemm_tf32_kernel<0><<<gridR, 256, GEMM_SMEM>>>(pR, WQr, pRq, nR, nullptr, nullptr);
        gemm_tf32_kernel<0><<<gridR, 256, GEMM_SMEM>>>(pR, WKr, pRk, nR, nullptr, nullptr);
        gemm_tf32_kernel<0><<<gridR, 256, GEMM_SMEM>>>(pR, WVr, pRv, nR, nullptr, nullptr);

        // atoms attend to residues: Q=Aq (<=64 rows per complex), K/V = Rk/Rv
        attn_mma_kernel<<<dim3(256, 1), 256, ATT_SMEM>>>(pAq, pRk, pRv, pTA, lig, res);
        // residues attend to atoms: Q=Rq (chunks of 64), K/V = Ak/Av
        attn_mma_kernel<<<dim3(256, 8), 256, ATT_SMEM>>>(pRq, pAk, pAv, pTR, res, lig);

        gemm_tf32_kernel<2><<<gridA, 256, GEMM_SMEM>>>(pTA, WOl, pA, nA, pInvA, pA);
        gemm_tf32_kernel<2><<<gridR, 256, GEMM_SMEM>>>(pTR, WOr, pR, nR, pInvR, pR);
    }

    copy_out_kernel<<<1024, 256>>>((float*)d_out, nA, nR);
}

// round 4
// speedup vs baseline: 2.2905x; 1.0457x over previous
#include <cuda_runtime.h>
#include <cstdint>

#define DD 256
#define NA_MAX (64*256)
#define NR_MAX (512*256)

// ---------------- scratch state (device globals; no allocation) ----------------
__device__ __align__(16) float gA [NA_MAX*DD];
__device__ __align__(16) float gR [NR_MAX*DD];
__device__ __align__(16) float gAq[NA_MAX*DD];
__device__ __align__(16) float gAk[NA_MAX*DD];
__device__ __align__(16) float gAv[NA_MAX*DD];
__device__ __align__(16) float gRq[NR_MAX*DD];
__device__ __align__(16) float gRk[NR_MAX*DD];
__device__ __align__(16) float gRv[NR_MAX*DD];
__device__ __align__(16) float gTA[NA_MAX*DD];
__device__ __align__(16) float gTR[NR_MAX*DD];
__device__ float gInvA[NA_MAX];
__device__ float gInvR[NR_MAX];
__device__ __align__(16) float gWh[10*DD*DD];   // presplit weights, tf32-hi
__device__ __align__(16) float gWl[10*DD*DD];   // presplit weights, tf32-lo

__device__ __forceinline__ float leaky_f(float x) { return x >= 0.f ? x : 0.1f * x; }
__device__ __forceinline__ float sigmoid_f(float x) {
    return __fdividef(1.f, 1.f + __expf(-x));
}
__device__ __forceinline__ float to_tf32(float x) {
    uint32_t u;
    asm("cvt.rna.tf32.f32 %0, %1;" : "=r"(u) : "f"(x));
    return __uint_as_float(u);
}
__device__ __forceinline__ void split_tf32(float x, float& hi, float& lo) {
    uint32_t u;
    asm("cvt.rna.tf32.f32 %0, %1;" : "=r"(u) : "f"(x));
    hi = __uint_as_float(u);
    float r = x - hi;
    uint32_t v;
    asm("cvt.rna.tf32.f32 %0, %1;" : "=r"(v) : "f"(r));
    lo = __uint_as_float(v);
}
__device__ __forceinline__ void mma_tf32(float* d, const uint32_t* a, const uint32_t* b) {
    asm volatile(
        "mma.sync.aligned.m16n8k8.row.col.f32.tf32.tf32.f32 "
        "{%0,%1,%2,%3}, {%4,%5,%6,%7}, {%8,%9}, {%0,%1,%2,%3};\n"
        : "+f"(d[0]), "+f"(d[1]), "+f"(d[2]), "+f"(d[3])
        : "r"(a[0]), "r"(a[1]), "r"(a[2]), "r"(a[3]), "r"(b[0]), "r"(b[1]));
}
__device__ __forceinline__ uint32_t smem_u32(const void* p) {
    return (uint32_t)__cvta_generic_to_shared(p);
}
__device__ __forceinline__ void cp16(uint32_t s, const void* g) {
    asm volatile("cp.async.cg.shared.global [%0], [%1], 16;\n" :: "r"(s), "l"(g));
}
__device__ __forceinline__ void cp_commit() { asm volatile("cp.async.commit_group;\n"); }
template <int N> __device__ __forceinline__ void cp_wait() {
    asm volatile("cp.async.wait_group %0;\n" :: "n"(N));
}

// ---------------- per-row 1/count scales ----------------
__global__ void fill_inv_kernel(const int* __restrict__ lig, const int* __restrict__ res) {
    int b = blockIdx.x;
    int as = lig[2*b], ac = lig[2*b+1];
    int rs = res[2*b], rc = res[2*b+1];
    float ia = 1.f / (float)rc;
    float ir = 1.f / (float)ac;
    for (int i = threadIdx.x; i < ac; i += blockDim.x) gInvA[as + i] = ia;
    for (int i = threadIdx.x; i < rc; i += blockDim.x) gInvR[rs + i] = ir;
}

// ---------------- weight presplit: 10 weights -> hi/lo tf32 ----------------
struct WIn { const float* w[10]; };
__global__ void presplit_kernel(WIn win, float* __restrict__ wh, float* __restrict__ wl) {
    int i = blockIdx.x * 256 + threadIdx.x;
    if (i >= 10 * DD * DD) return;
    int wi = i >> 16, off = i & 65535;
    float h, l;
    split_tf32(win.w[wi][off], h, l);
    wh[i] = h; wl[i] = l;
}

// ---------------- fused 3xTF32 pipelined GEMM ----------------
// Covers both sides (A-rows then R-rows in grid.x) and NW weights (grid.y = NW*4).
// MODE 0: C = XW ; MODE 1: C = leaky(XW) ; MODE 2: C = leaky(XW)*scale[r] + base[r,c]
struct GArgs {
    const float* X[2];
    const float* Wh[2][3];
    const float* Wl[2][3];
    float*       C[2][3];
    const float* scale[2];
    const float* base[2];
    int M[2];
    int aTiles;
};

#define GX_STR 36
#define GW_STR 72
#define G_STAGE (128*GX_STR + 2*32*GW_STR)     // floats per stage (9216)
#define GEMM_SMEM (2*G_STAGE*4)                // 73728 B

__device__ __forceinline__ void gemm_stage(const float* X, const float* Wh, const float* Wl,
                                           float* sX, float* sWh, float* sWl,
                                           int row0, int M, int col0, int k0, int tid)
{
    #pragma unroll
    for (int i = 0; i < 4; i++) {
        int idx = tid + 256 * i;
        int row = idx >> 3, ch = idx & 7;
        int grow = row0 + row; if (grow > M - 1) grow = M - 1;   // clamp: garbage rows never stored
        cp16(smem_u32(sX + row * GX_STR + ch * 4), X + (size_t)grow * DD + k0 + ch * 4);
    }
    #pragma unroll
    for (int i = 0; i < 2; i++) {
        int idx = tid + 256 * i;
        int row = idx >> 4, ch = idx & 15;
        cp16(smem_u32(sWh + row * GW_STR + ch * 4), Wh + (size_t)(k0 + row) * DD + col0 + ch * 4);
        cp16(smem_u32(sWl + row * GW_STR + ch * 4), Wl + (size_t)(k0 + row) * DD + col0 + ch * 4);
    }
}

template <int MODE, int NW>
__global__ void gemm_fused_kernel(GArgs g)
{
    extern __shared__ float smf[];
    const int side = (blockIdx.x >= g.aTiles) ? 1 : 0;
    const int rt = side ? blockIdx.x - g.aTiles : blockIdx.x;
    const int w = blockIdx.y >> 2;
    const int col0 = (blockIdx.y & 3) * 64;
    const int M = g.M[side];
    const int row0 = rt * 128;
    const float* X  = g.X[side];
    const float* Wh = g.Wh[side][w];
    const float* Wl = g.Wl[side][w];
    float* C = g.C[side][w];

    const int tid = threadIdx.x, lane = tid & 31, warp = tid >> 5;
    const int wm = warp >> 1, wn = warp & 1;
    const int lq = lane >> 2, lr = lane & 3;

    float* sX[2]; float* sWh[2]; float* sWl[2];
    sX[0] = smf;            sWh[0] = sX[0] + 128 * GX_STR; sWl[0] = sWh[0] + 32 * GW_STR;
    sX[1] = smf + G_STAGE;  sWh[1] = sX[1] + 128 * GX_STR; sWl[1] = sWh[1] + 32 * GW_STR;

    float acc[2][4][4] = {};

    gemm_stage(X, Wh, Wl, sX[0], sWh[0], sWl[0], row0, M, col0, 0, tid);
    cp_commit();

    for (int t = 0; t < 8; t++) {
        int buf = t & 1;
        if (t < 7) {
            gemm_stage(X, Wh, Wl, sX[buf ^ 1], sWh[buf ^ 1], sWl[buf ^ 1],
                       row0, M, col0, (t + 1) * 32, tid);
            cp_commit();
            cp_wait<1>();
        } else {
            cp_wait<0>();
        }
        __syncthreads();

        #pragma unroll
        for (int kk = 0; kk < 4; kk++) {
            uint32_t ah[2][4], al[2][4], bh[4][2], bl[4][2];
            #pragma unroll
            for (int mf = 0; mf < 2; mf++) {
                const float* xb = sX[buf] + (wm * 32 + mf * 16 + lq) * GX_STR + kk * 8 + lr;
                float raw[4];
                raw[0] = xb[0]; raw[1] = xb[8 * GX_STR];
                raw[2] = xb[4]; raw[3] = xb[8 * GX_STR + 4];
                #pragma unroll
                for (int e = 0; e < 4; e++) {
                    float h, l;
                    split_tf32(raw[e], h, l);
                    ah[mf][e] = __float_as_uint(h);
                    al[mf][e] = __float_as_uint(l);
                }
            }
            #pragma unroll
            for (int nf = 0; nf < 4; nf++) {
                int n = wn * 32 + nf * 8 + lq;
                int k = kk * 8 + lr;
                bh[nf][0] = __float_as_uint(sWh[buf][k * GW_STR + n]);
                bh[nf][1] = __float_as_uint(sWh[buf][(k + 4) * GW_STR + n]);
                bl[nf][0] = __float_as_uint(sWl[buf][k * GW_STR + n]);
                bl[nf][1] = __float_as_uint(sWl[buf][(k + 4) * GW_STR + n]);
            }
            #pragma unroll
            for (int mf = 0; mf < 2; mf++)
                #pragma unroll
                for (int nf = 0; nf < 4; nf++) {
                    mma_tf32(acc[mf][nf], al[mf], bh[nf]);
                    mma_tf32(acc[mf][nf], ah[mf], bl[nf]);
                    mma_tf32(acc[mf][nf], ah[mf], bh[nf]);
                }
        }
        __syncthreads();
    }

    #pragma unroll
    for (int mf = 0; mf < 2; mf++) {
        #pragma unroll
        for (int i = 0; i < 4; i++) {
            int r = row0 + wm * 32 + mf * 16 + lq + ((i >= 2) ? 8 : 0);
            if (r >= M) continue;
            float sc = (MODE == 2) ? g.scale[side][r] : 0.f;
            #pragma unroll
            for (int nf = 0; nf < 4; nf++) {
                int c = col0 + wn * 32 + nf * 8 + lr * 2 + (i & 1);
                float v = acc[mf][nf][i];
                if (MODE == 1) v = leaky_f(v);
                if (MODE == 2) v = leaky_f(v) * sc + g.base[side][(size_t)r * DD + c];
                C[(size_t)r * DD + c] = v;
            }
        }
    }
}

// ---------------- mma sigmoid attention, cp.async pipelined, permuted Q ----------------
// Block: (complex b, 64-row query chunk). O[q,:] = sum_kv sigmoid(Q[q].K[kv]) * V[kv,:]
#define KV_STR 264
#define SSTR2 40
// smem floats: Qp 16384 | sS 64*40 | regionA (K+V 16896) | regionB (16896)
#define ATT_QP 0
#define ATT_SS 16384
#define ATT_RA (16384 + 64*SSTR2)
#define ATT_RB (ATT_RA + 2*32*KV_STR)
#define ATT_SMEM ((ATT_RB + 2*32*KV_STR) * 4)   // 210944 B

__device__ __forceinline__ void attn_stage_kv(const float* K, const float* V,
                                              float* regKb, float* regVb,
                                              size_t kv0, int t0, int kvc, int tid)
{
    #pragma unroll
    for (int i = 0; i < 8; i++) {
        int idx = tid + 256 * i;
        int row = idx >> 6, ch = idx & 63;
        int gr = t0 + row; if (gr > kvc - 1) gr = kvc - 1;   // clamp: masked later
        cp16(smem_u32(regKb + row * KV_STR + ch * 4), K + (kv0 + gr) * DD + ch * 4);
        cp16(smem_u32(regVb + row * KV_STR + ch * 4), V + (kv0 + gr) * DD + ch * 4);
    }
}

__global__ void attn_mma_kernel(const float* __restrict__ Q, const float* __restrict__ K,
                                const float* __restrict__ V, float* __restrict__ O,
                                const int* __restrict__ scQ, const int* __restrict__ scKV)
{
    extern __shared__ float smf[];
    float* Qp = smf + ATT_QP;
    float* sS = smf + ATT_SS;
    float* regK[2]; float* regV[2];
    regK[0] = smf + ATT_RA; regV[0] = regK[0] + 32 * KV_STR;
    regK[1] = smf + ATT_RB; regV[1] = regK[1] + 32 * KV_STR;
    float* Qraw = regK[0];   // region A aliased for the initial Q staging (exactly 64*KV_STR floats)

    const int b = blockIdx.x;
    const int qs0 = scQ[2*b], qc = scQ[2*b+1];
    const int kv0i = scKV[2*b], kvc = scKV[2*b+1];
    const int qbeg = blockIdx.y * 64;
    if (qbeg >= qc) return;
    const int qcnt = (qc - qbeg < 64) ? (qc - qbeg) : 64;

    const int tid = threadIdx.x, lane = tid & 31, warp = tid >> 5;
    const int lq = lane >> 2, lr = lane & 3;

    // ---- stage Q (raw) into region A ----
    #pragma unroll
    for (int i = 0; i < 16; i++) {
        int idx = tid + 256 * i;
        int row = idx >> 6, ch = idx & 63;
        int gr = qbeg + row; if (gr > qc - 1) gr = qc - 1;
        cp16(smem_u32(Qraw + row * KV_STR + ch * 4), Q + (size_t)(qs0 + gr) * DD + ch * 4);
    }
    cp_commit();
    // ---- prefetch KV tile 0 into region B ----
    attn_stage_kv(K, V, regK[1], regV[1], (size_t)kv0i, 0, kvc, tid);
    cp_commit();

    cp_wait<1>();           // Q arrived (KV0 may still be in flight)
    __syncthreads();

    // ---- permute Q into fragment-major Qp (with tf32 round) ----
    {
        int mt = warp >> 1;
        #pragma unroll
        for (int i = 0; i < 16; i++) {
            int kk = (warp & 1) * 16 + i;
            const float* qb = Qraw + (mt * 16 + lq) * KV_STR + kk * 8 + lr;
            float4 v;
            v.x = to_tf32(qb[0]);
            v.y = to_tf32(qb[8 * KV_STR]);
            v.z = to_tf32(qb[4]);
            v.w = to_tf32(qb[8 * KV_STR + 4]);
            *(float4*)(Qp + ((size_t)(mt * 32 + kk) * 32 + lane) * 4) = v;
        }
    }
    __syncthreads();        // region A free; stage 1 may now be written there

    float o[4][4][4] = {};
    const int nT = (kvc + 31) >> 5;

    for (int t = 0; t < nT; t++) {
        int buf = (t & 1) ^ 1;      // t=0 -> region B
        if (t + 1 < nT) {
            attn_stage_kv(K, V, regK[buf ^ 1], regV[buf ^ 1], (size_t)kv0i, (t + 1) * 32, kvc, tid);
            cp_commit();
            cp_wait<1>();
        } else {
            cp_wait<0>();
        }
        __syncthreads();

        int klim = kvc - t * 32; if (klim > 32) klim = 32;

        // ---- phase S: 64x32 scores, K=256 ----
        {
            const int wm = warp >> 1, wn = warp & 1;
            const int m0 = wm * 16, n0 = wn * 16;
            float s[2][4] = {};
            #pragma unroll 4
            for (int kk = 0; kk < 32; kk++) {
                float4 qv = *(const float4*)(Qp + ((size_t)(wm * 32 + kk) * 32 + lane) * 4);
                uint32_t a[4] = { __float_as_uint(qv.x), __float_as_uint(qv.y),
                                  __float_as_uint(qv.z), __float_as_uint(qv.w) };
                uint32_t bb[2][2];
                #pragma unroll
                for (int nf = 0; nf < 2; nf++) {
                    const float* kp = regK[buf] + (n0 + nf * 8 + lq) * KV_STR + kk * 8 + lr;
                    bb[nf][0] = __float_as_uint(to_tf32(kp[0]));
                    bb[nf][1] = __float_as_uint(to_tf32(kp[4]));
                }
                mma_tf32(s[0], a, bb[0]);
                mma_tf32(s[1], a, bb[1]);
            }
            #pragma unroll
            for (int nf = 0; nf < 2; nf++)
                #pragma unroll
                for (int e = 0; e < 4; e++) {
                    int row = m0 + lq + ((e >= 2) ? 8 : 0);
                    int col = n0 + nf * 8 + lr * 2 + (e & 1);
                    float v = (col < klim) ? sigmoid_f(s[nf][e]) : 0.f;
                    sS[row * SSTR2 + col] = to_tf32(v);
                }
        }
        __syncthreads();

        // ---- phase PV: O += S @ V (each warp owns 32 feature cols) ----
        {
            const int n0 = warp * 32;
            #pragma unroll
            for (int ks = 0; ks < 4; ks++) {
                uint32_t a[4][4], bb[4][2];
                #pragma unroll
                for (int mf = 0; mf < 4; mf++) {
                    const float* sp = sS + (mf * 16 + lq) * SSTR2 + ks * 8 + lr;
                    a[mf][0] = __float_as_uint(sp[0]);
                    a[mf][1] = __float_as_uint(sp[8 * SSTR2]);
                    a[mf][2] = __float_as_uint(sp[4]);
                    a[mf][3] = __float_as_uint(sp[8 * SSTR2 + 4]);
                }
                #pragma unroll
                for (int nf = 0; nf < 4; nf++) {
                    const float* vp = regV[buf] + (ks * 8 + lr) * KV_STR + n0 + nf * 8 + lq;
                    bb[nf][0] = __float_as_uint(to_tf32(vp[0]));
                    bb[nf][1] = __float_as_uint(to_tf32(vp[4 * KV_STR]));
                }
                #pragma unroll
                for (int mf = 0; mf < 4; mf++)
                    #pragma unroll
                    for (int nf = 0; nf < 4; nf++)
                        mma_tf32(o[mf][nf], a[mf], bb[nf]);
            }
        }
        __syncthreads();
    }

    // ---- store O ----
    const int n0 = warp * 32;
    float* Obase = O + (size_t)(qs0 + qbeg) * DD;
    #pragma unroll
    for (int mf = 0; mf < 4; mf++)
        #pragma unroll
        for (int e = 0; e < 4; e++) {
            int row = mf * 16 + lq + ((e >= 2) ? 8 : 0);
            if (row >= qcnt) continue;
            #pragma unroll
            for (int nf = 0; nf < 4; nf++) {
                int col = n0 + nf * 8 + lr * 2 + (e & 1);
                Obase[(size_t)row * DD + col] = o[mf][nf][e];
            }
        }
}

// ---------------- final output: concat(A_flat, R_flat) ----------------
__global__ void copy_out_kernel(float* __restrict__ out, int nA, int nR) {
    size_t na4 = (size_t)nA * DD / 4;
    size_t tot = (size_t)(nA + nR) * DD / 4;
    const float4* a4 = (const float4*)gA;
    const float4* r4 = (const float4*)gR;
    for (size_t i = blockIdx.x * (size_t)blockDim.x + threadIdx.x; i < tot;
         i += (size_t)gridDim.x * blockDim.x) {
        ((float4*)out)[i] = (i < na4) ? a4[i] : r4[i - na4];
    }
}

// ---------------- host launch ----------------
extern "C" void kernel_launch(void* const* d_in, const int* in_sizes, int n_in,
                              void* d_out, int out_size) {
    const float* fatoms = (const float*)d_in[0];
    const float* fres   = (const float*)d_in[1];
    const int* lig = (const int*)d_in[12];
    const int* res = (const int*)d_in[13];

    int nA = in_sizes[0] / DD;
    int nR = in_sizes[1] / DD;

    float *pA, *pR, *pAq, *pAk, *pAv, *pRq, *pRk, *pRv, *pTA, *pTR, *pInvA, *pInvR, *pWh, *pWl;
    cudaGetSymbolAddress((void**)&pA,  gA);
    cudaGetSymbolAddress((void**)&pR,  gR);
    cudaGetSymbolAddress((void**)&pAq, gAq);
    cudaGetSymbolAddress((void**)&pAk, gAk);
    cudaGetSymbolAddress((void**)&pAv, gAv);
    cudaGetSymbolAddress((void**)&pRq, gRq);
    cudaGetSymbolAddress((void**)&pRk, gRk);
    cudaGetSymbolAddress((void**)&pRv, gRv);
    cudaGetSymbolAddress((void**)&pTA, gTA);
    cudaGetSymbolAddress((void**)&pTR, gTR);
    cudaGetSymbolAddress((void**)&pInvA, gInvA);
    cudaGetSymbolAddress((void**)&pInvR, gInvR);
    cudaGetSymbolAddress((void**)&pWh, gWh);
    cudaGetSymbolAddress((void**)&pWl, gWl);

    cudaFuncSetAttribute(gemm_fused_kernel<0,3>, cudaFuncAttributeMaxDynamicSharedMemorySize, GEMM_SMEM);
    cudaFuncSetAttribute(gemm_fused_kernel<1,1>, cudaFuncAttributeMaxDynamicSharedMemorySize, GEMM_SMEM);
    cudaFuncSetAttribute(gemm_fused_kernel<2,1>, cudaFuncAttributeMaxDynamicSharedMemorySize, GEMM_SMEM);
    cudaFuncSetAttribute(attn_mma_kernel, cudaFuncAttributeMaxDynamicSharedMemorySize, ATT_SMEM);

    // weight slot order: 0=W_lig_t 1=WQl 2=WKl 3=WVl 4=WOl | 5=W_res_t 6=WQr 7=WKr 8=WVr 9=WOr
    WIn win;
    win.w[0] = (const float*)d_in[2];   // W_lig_t
    win.w[1] = (const float*)d_in[4];   // WQl
    win.w[2] = (const float*)d_in[5];   // WKl
    win.w[3] = (const float*)d_in[6];   // WVl
    win.w[4] = (const float*)d_in[7];   // WOl
    win.w[5] = (const float*)d_in[3];   // W_res_t
    win.w[6] = (const float*)d_in[8];   // WQr
    win.w[7] = (const float*)d_in[9];   // WKr
    win.w[8] = (const float*)d_in[10];  // WVr
    win.w[9] = (const float*)d_in[11];  // WOr

    const int aTiles = (nA + 127) / 128;
    const int rTiles = (nR + 127) / 128;
    const int W = DD * DD;

    fill_inv_kernel<<<256, 256>>>(lig, res);
    presplit_kernel<<<(10 * W + 255) / 256, 256>>>(win, pWh, pWl);

    // input transforms (fused A+R): A0 = leaky(fatoms@W_lig_t), R0 = leaky(fres@W_res_t)
    GArgs gi = {};
    gi.X[0] = fatoms; gi.X[1] = fres;
    gi.Wh[0][0] = pWh + 0 * W; gi.Wl[0][0] = pWl + 0 * W;
    gi.Wh[1][0] = pWh + 5 * W; gi.Wl[1][0] = pWl + 5 * W;
    gi.C[0][0] = pA; gi.C[1][0] = pR;
    gi.M[0] = nA; gi.M[1] = nR; gi.aTiles = aTiles;

    // fused QKV projections
    GArgs gq = {};
    gq.X[0] = pA; gq.X[1] = pR;
    for (int j = 0; j < 3; j++) {
        gq.Wh[0][j] = pWh + (1 + j) * W; gq.Wl[0][j] = pWl + (1 + j) * W;
        gq.Wh[1][j] = pWh + (6 + j) * W; gq.Wl[1][j] = pWl + (6 + j) * W;
    }
    gq.C[0][0] = pAq; gq.C[0][1] = pAk; gq.C[0][2] = pAv;
    gq.C[1][0] = pRq; gq.C[1][1] = pRk; gq.C[1][2] = pRv;
    gq.M[0] = nA; gq.M[1] = nR; gq.aTiles = aTiles;

    // fused output GEMMs: A = leaky(TA@WOl)*invA + A ; R = leaky(TR@WOr)*invR + R
    GArgs go = {};
    go.X[0] = pTA; go.X[1] = pTR;
    go.Wh[0][0] = pWh + 4 * W; go.Wl[0][0] = pWl + 4 * W;
    go.Wh[1][0] = pWh + 9 * W; go.Wl[1][0] = pWl + 9 * W;
    go.C[0][0] = pA; go.C[1][0] = pR;
    go.scale[0] = pInvA; go.scale[1] = pInvR;
    go.base[0] = pA; go.base[1] = pR;
    go.M[0] = nA; go.M[1] = nR; go.aTiles = aTiles;

    dim3 gridInit(aTiles + rTiles, 4);
    dim3 gridQKV(aTiles + rTiles, 12);
    dim3 gridOut(aTiles + rTiles, 4);

    gemm_fused_kernel<1,1><<<gridInit, 256, GEMM_SMEM>>>(gi);

    for (int it = 0; it < 3; it++) {
        gemm_fused_kernel<0,3><<<gridQKV, 256, GEMM_SMEM>>>(gq);

        // atoms attend to residues: Q=Aq (<=64 rows/complex), K/V = Rk/Rv
        attn_mma_kernel<<<dim3(256, 1), 256, ATT_SMEM>>>(pAq, pRk, pRv, pTA, lig, res);
        // residues attend to atoms: Q=Rq (64-row chunks), K/V = Ak/Av
        attn_mma_kernel<<<dim3(256, 8), 256, ATT_SMEM>>>(pRq, pAk, pAv, pTR, res, lig);

        gemm_fused_kernel<2,1><<<gridOut, 256, GEMM_SMEM>>>(go);
    }

    copy_out_kernel<<<1024, 256>>>((float*)d_out, nA, nR);
}